// round 12
// baseline (speedup 1.0000x reference)
#include <cuda_runtime.h>
#include <stdint.h>

#define N_NODES 100000
#define E_EDGES 1600000
#define HID 64
#define SCAN_B 512

// ---------------- scratch (no allocation allowed) ----------------
__device__ float g_bufA[N_NODES * HID];        // dinv-scaled GEMM out
__device__ float g_bufB[N_NODES * HID];        // layer output h
__device__ float g_dinv[N_NODES];
__device__ int   g_cnt[N_NODES];               // per-dst edge counts
__device__ int   g_off[N_NODES + 1];           // CSR offsets
__device__ int   g_cur[N_NODES];               // fill cursors (init from off)
__device__ int   g_bsum[(N_NODES + SCAN_B - 1) / SCAN_B];
__device__ int   g_csr[E_EDGES];               // src indices sorted by dst
__device__ int   g_is64;                       // 1 if edge_index is int64

__device__ __forceinline__ float lrelu1(float v) {
    return fmaxf(v, 0.f) + 0.01f * fminf(v, 0.f);
}

// ---------------- dtype detection ----------
__global__ void k_detect(const unsigned int* __restrict__ u32buf) {
    __shared__ unsigned int s_or[256];
    unsigned int acc = 0;
    for (int i = threadIdx.x; i < 2048; i += 256)
        acc |= u32buf[2 * i + 1];          // hi word of candidate int64 #i
    s_or[threadIdx.x] = acc;
    __syncthreads();
    for (int s = 128; s > 0; s >>= 1) {
        if (threadIdx.x < s) s_or[threadIdx.x] |= s_or[threadIdx.x + s];
        __syncthreads();
    }
    if (threadIdx.x == 0) g_is64 = (s_or[0] == 0) ? 1 : 0;
}

__device__ __forceinline__ int load_idx(const unsigned int* u32buf, long long elem, int is64, int n) {
    unsigned int v = is64 ? u32buf[2 * elem] : u32buf[elem];
    int iv = (int)v;
    return min(max(iv, 0), n - 1);
}

// ---------------- graph precompute ----------------
__global__ void k_zero(int* __restrict__ cnt, int n) {
    int i = blockIdx.x * blockDim.x + threadIdx.x;
    if (i < n) cnt[i] = 0;
}

__global__ void k_count(const unsigned int* __restrict__ ei, int* __restrict__ cnt,
                        int E, int n) {
    int e = blockIdx.x * blockDim.x + threadIdx.x;
    if (e < E) {
        int is64 = g_is64;
        int d = load_idx(ei, (long long)E + e, is64, n);
        atomicAdd(cnt + d, 1);
    }
}

// ---------------- scan over cnt -> off, fused dinv ----------------
__global__ void k_scan_block(const int* __restrict__ cnt, int* __restrict__ off,
                             int* __restrict__ bsum, float* __restrict__ dinv, int n) {
    __shared__ int s[SCAN_B];
    int i = blockIdx.x * SCAN_B + threadIdx.x;
    int v = (i < n) ? cnt[i] : 0;
    if (i < n) dinv[i] = rsqrtf(1.0f + (float)v);       // +1 self loop (fused)
    s[threadIdx.x] = v;
    __syncthreads();
#pragma unroll
    for (int d = 1; d < SCAN_B; d <<= 1) {
        int t = (threadIdx.x >= d) ? s[threadIdx.x - d] : 0;
        __syncthreads();
        s[threadIdx.x] += t;
        __syncthreads();
    }
    if (i < n) off[i] = s[threadIdx.x] - v;             // exclusive within block
    if (threadIdx.x == SCAN_B - 1) bsum[blockIdx.x] = s[SCAN_B - 1];
}

__global__ void k_scan_bsum(int* __restrict__ bsum, int nb) {   // nb <= SCAN_B
    __shared__ int s[SCAN_B];
    int v = (threadIdx.x < nb) ? bsum[threadIdx.x] : 0;
    s[threadIdx.x] = v;
    __syncthreads();
#pragma unroll
    for (int d = 1; d < SCAN_B; d <<= 1) {
        int t = (threadIdx.x >= d) ? s[threadIdx.x - d] : 0;
        __syncthreads();
        s[threadIdx.x] += t;
        __syncthreads();
    }
    if (threadIdx.x < nb) bsum[threadIdx.x] = s[threadIdx.x] - v;   // exclusive
}

__global__ void k_scan_add(int* __restrict__ off, int* __restrict__ cur,
                           const int* __restrict__ bsum, int n, int E) {
    int i = blockIdx.x * blockDim.x + threadIdx.x;
    if (i < n) {
        int o = off[i] + bsum[i / SCAN_B];
        off[i] = o;
        cur[i] = o;
    }
    if (i == 0) off[n] = E;
}

// ---------------- CSR fill (src index only; no norms) ----------------
__global__ void k_fill(const unsigned int* __restrict__ ei,
                       int* __restrict__ cur, int* __restrict__ csr, int E, int n) {
    int e = blockIdx.x * blockDim.x + threadIdx.x;
    if (e < E) {
        int is64 = g_is64;
        int s = load_idx(ei, e, is64, n);
        int d = load_idx(ei, (long long)E + e, is64, n);
        int pos = atomicAdd(cur + d, 1);
        csr[pos] = s;
    }
}

// ---------------- GEMM: out[n,64] = dinv[row] * (in[n,64] @ W[64,64]) ------
// v4 column-split: 256 threads = 8 warps per block; 128 rows per block.
// Warps 0-3: cols [0,32) for rows; warps 4-7: cols [32,64) for same rows.
// 32 accumulators/thread (~64 regs -> 2x occupancy of v2), W pointer is
// warp-uniform so all smem reads stay broadcast.
__global__ __launch_bounds__(256)
void k_gemm64(const float* __restrict__ in, const float* __restrict__ W,
              const float* __restrict__ dinvv, float* __restrict__ out, int n) {
    __shared__ float Ws[64 * 64];
    for (int i = threadIdx.x; i < 64 * 16; i += 256)
        ((float4*)Ws)[i] = ((const float4*)W)[i];
    __syncthreads();

    int warp = threadIdx.x >> 5;           // 0..7
    int lane = threadIdx.x & 31;
    int colbase = (warp >> 2) * 32;        // 0 or 32 (warp-uniform)
    int row = blockIdx.x * 128 + (warp & 3) * 32 + lane;
    if (row >= n) return;

    float acc[32];
#pragma unroll
    for (int j = 0; j < 32; j++) acc[j] = 0.f;

    const float4* inr = (const float4*)(in + (size_t)row * HID);

#pragma unroll 4
    for (int k4 = 0; k4 < 16; k4++) {
        float4 v = inr[k4];
        float av[4] = {v.x, v.y, v.z, v.w};
#pragma unroll
        for (int kk = 0; kk < 4; kk++) {
            const float* wrow = Ws + (k4 * 4 + kk) * 64 + colbase;
#pragma unroll
            for (int j = 0; j < 32; j++)
                acc[j] = fmaf(av[kk], wrow[j], acc[j]);
        }
    }

    float di = __ldg(dinvv + row);
    float4* outr = (float4*)(out + (size_t)row * HID + colbase);
#pragma unroll
    for (int j = 0; j < 8; j++)
        outr[j] = make_float4(di * acc[4 * j], di * acc[4 * j + 1],
                              di * acc[4 * j + 2], di * acc[4 * j + 3]);
}

// ---------------- gather: h[node] = lrelu(dinv[node]*(bufA[node]
//                                    + sum_e bufA[src_e]) + bias) ----------
// One warp per destination node; lane owns 2 feature columns (float2).
__global__ __launch_bounds__(256)
void k_gather(const float* __restrict__ lin, const int* __restrict__ csr,
              const int* __restrict__ off, const float* __restrict__ dinv,
              const float* __restrict__ bias, float* __restrict__ outp, int n) {
    int warp = (blockIdx.x * blockDim.x + threadIdx.x) >> 5;
    int lane = threadIdx.x & 31;
    if (warp >= n) return;
    int node = warp;

    int beg = __ldg(off + node);
    int end = __ldg(off + node + 1);

    const float2* lin2 = (const float2*)lin;
    float2 t = __ldg(lin2 + (size_t)node * 32 + lane);   // self term (pre-scaled)
    float tx = t.x, ty = t.y;

    int i = beg;
    for (; i + 2 <= end; i += 2) {
        int s0 = __ldg(csr + i);
        int s1 = __ldg(csr + i + 1);
        float2 v0 = __ldg(lin2 + (size_t)s0 * 32 + lane);
        float2 v1 = __ldg(lin2 + (size_t)s1 * 32 + lane);
        tx += v0.x; ty += v0.y;
        tx += v1.x; ty += v1.y;
    }
    if (i < end) {
        int s0 = __ldg(csr + i);
        float2 v0 = __ldg(lin2 + (size_t)s0 * 32 + lane);
        tx += v0.x; ty += v0.y;
    }

    float di = __ldg(dinv + node);
    float2 b = __ldg(((const float2*)bias) + lane);
    float2 o;
    o.x = lrelu1(fmaf(di, tx, b.x));
    o.y = lrelu1(fmaf(di, ty, b.y));
    ((float2*)outp)[(size_t)node * 32 + lane] = o;
}

// ---------------- launch ----------------
extern "C" void kernel_launch(void* const* d_in, const int* in_sizes, int n_in,
                              void* d_out, int out_size) {
    const float*        x  = (const float*)d_in[0];
    const unsigned int* ei = (const unsigned int*)d_in[1];
    const float*        W1 = (const float*)d_in[2];
    const float*        b1 = (const float*)d_in[3];
    const float*        W2 = (const float*)d_in[4];
    const float*        b2 = (const float*)d_in[5];
    const float*        W3 = (const float*)d_in[6];
    const float*        b3 = (const float*)d_in[7];
    float* out = (float*)d_out;

    const int n = in_sizes[0] / HID;        // 100000
    const int E = in_sizes[1] / 2;          // 1600000

    float* bufA;  cudaGetSymbolAddress((void**)&bufA, g_bufA);
    float* bufB;  cudaGetSymbolAddress((void**)&bufB, g_bufB);
    float* dinv;  cudaGetSymbolAddress((void**)&dinv, g_dinv);
    int*   cnt;   cudaGetSymbolAddress((void**)&cnt,  g_cnt);
    int*   off;   cudaGetSymbolAddress((void**)&off,  g_off);
    int*   cur;   cudaGetSymbolAddress((void**)&cur,  g_cur);
    int*   bsum;  cudaGetSymbolAddress((void**)&bsum, g_bsum);
    int*   csr;   cudaGetSymbolAddress((void**)&csr,  g_csr);

    const int T = 256;
    int gn  = (n + T - 1) / T;
    int gE  = (E + T - 1) / T;
    int nb  = (n + SCAN_B - 1) / SCAN_B;     // 196
    int gGem = (n + 127) / 128;              // 128 rows per 256-thread block
    int gGat = (n * 32 + T - 1) / T;         // warp per node

    // dtype detection + CSR build
    k_detect<<<1, 256>>>(ei);
    k_zero<<<gn, T>>>(cnt, n);
    k_count<<<gE, T>>>(ei, cnt, E, n);
    k_scan_block<<<nb, SCAN_B>>>(cnt, off, bsum, dinv, n);
    k_scan_bsum<<<1, SCAN_B>>>(bsum, nb);
    k_scan_add<<<gn, T>>>(off, cur, bsum, n, E);
    k_fill<<<gE, T>>>(ei, cur, csr, E, n);

    // layer 1
    k_gemm64<<<gGem, T>>>(x, W1, dinv, bufA, n);
    k_gather<<<gGat, T>>>(bufA, csr, off, dinv, b1, bufB, n);
    // layer 2
    k_gemm64<<<gGem, T>>>(bufB, W2, dinv, bufA, n);
    k_gather<<<gGat, T>>>(bufA, csr, off, dinv, b2, bufB, n);
    // layer 3 -> d_out directly (plain stores only)
    k_gemm64<<<gGem, T>>>(bufB, W3, dinv, bufA, n);
    k_gather<<<gGat, T>>>(bufA, csr, off, dinv, b3, out, n);
}